// round 16
// baseline (speedup 1.0000x reference)
#include <cuda_runtime.h>
#include <cstdint>

// ---------------- problem constants ----------------
#define BATCH    128
#define SEQLEN   16384
#define NBANDS   20
#define TAPS     513
#define PAD      512
#define EXTLEN   (SEQLEN + 2*PAD)            // 17408

// ---------------- FFT / overlap-save config ----------------
#define NFFT     4096
#define SEGSTEP  3072
#define NSEG     6
#define NPAIR    ((BATCH/2)*NSEG)            // 384
#define NT       256
#define NITEMS   (NBANDS*(BATCH/2)*NSEG)     // 7680
#define PCTAS    (148*4)                     // 592 persistent CTAs (4/SM)

// fwd smem: X[4096] Y[4096] T1[256] Ta[256] float2 = 68 KB
#define FWD_SH   ((4096*2 + 512) * 8)        // 69632
// inv smem: X[4096] T1[256] Ta[256] float2 = 36 KB
#define INV_SH   ((4096 + 512) * 8)          // 36864

// ---------------- device scratch ----------------
__device__ float2 g_spec[NPAIR * NFFT];
__device__ float  g_H[NBANDS * NFFT];

__device__ __forceinline__ int swz(int i) { return i ^ ((i >> 4) & 15); }

// FFMA-imm add/sub: x+y / x-y as fma(x, ±1.0, y) — rt_SMSP=1, bit-exact.
__device__ __forceinline__ float fadd1(float x, float y) {
    float r; asm("fma.rn.f32 %0, %1, 0f3F800000, %2;" : "=f"(r) : "f"(x), "f"(y)); return r;
}
__device__ __forceinline__ float fsub1(float x, float y) {   // x - y
    float r; asm("fma.rn.f32 %0, %1, 0fBF800000, %2;" : "=f"(r) : "f"(y), "f"(x)); return r;
}

__device__ __forceinline__ float2 cmul(float2 a, float2 b) {
    return make_float2(fmaf(a.x, b.x, -a.y * b.y), fmaf(a.x, b.y, a.y * b.x));
}
template <bool INV>
__device__ __forceinline__ float2 cmulc(float2 a, float cx, float cy) {
    if (INV) cy = -cy;
    float m = a.y * cy;
    float n = a.y * cx;
    return make_float2(fmaf(a.x, cx, -m), fmaf(a.x, cy, n));
}

template <bool INV>
__device__ __forceinline__ void dft4(float2& x0, float2& x1, float2& x2, float2& x3) {
    float t0x = fadd1(x0.x, x2.x), t0y = fadd1(x0.y, x2.y);
    float t1x = fsub1(x0.x, x2.x), t1y = fsub1(x0.y, x2.y);
    float t2x = fadd1(x1.x, x3.x), t2y = fadd1(x1.y, x3.y);
    float t3x = fsub1(x1.x, x3.x), t3y = fsub1(x1.y, x3.y);
    x0 = make_float2(fadd1(t0x, t2x), fadd1(t0y, t2y));
    x2 = make_float2(fsub1(t0x, t2x), fsub1(t0y, t2y));
    if (!INV) {
        x1 = make_float2(fadd1(t1x, t3y), fsub1(t1y, t3x));
        x3 = make_float2(fsub1(t1x, t3y), fadd1(t1y, t3x));
    } else {
        x1 = make_float2(fsub1(t1x, t3y), fadd1(t1y, t3x));
        x3 = make_float2(fadd1(t1x, t3y), fsub1(t1y, t3x));
    }
}

#define W1X  0.92387953251128674f
#define W1Y -0.38268343236508978f
#define W2X  0.70710678118654752f
#define W2Y -0.70710678118654752f
#define W3X  0.38268343236508978f
#define W3Y -0.92387953251128674f
#define W6X -0.70710678118654752f
#define W6Y -0.70710678118654752f
#define W9X -0.92387953251128674f
#define W9Y  0.38268343236508978f

template <bool INV>
__device__ __forceinline__ void dft16(float2* a) {
    #pragma unroll
    for (int n0 = 0; n0 < 4; n0++)
        dft4<INV>(a[n0], a[n0 + 4], a[n0 + 8], a[n0 + 12]);
    a[5]  = cmulc<INV>(a[5],  W1X, W1Y);
    a[9]  = cmulc<INV>(a[9],  W2X, W2Y);
    a[13] = cmulc<INV>(a[13], W3X, W3Y);
    a[6]  = cmulc<INV>(a[6],  W2X, W2Y);
    a[10] = INV ? make_float2(-a[10].y, a[10].x) : make_float2(a[10].y, -a[10].x);
    a[14] = cmulc<INV>(a[14], W6X, W6Y);
    a[7]  = cmulc<INV>(a[7],  W3X, W3Y);
    a[11] = cmulc<INV>(a[11], W6X, W6Y);
    a[15] = cmulc<INV>(a[15], W9X, W9Y);
    #pragma unroll
    for (int k0 = 0; k0 < 4; k0++)
        dft4<INV>(a[4 * k0], a[4 * k0 + 1], a[4 * k0 + 2], a[4 * k0 + 3]);
}
#define PERM(t) ((((t) & 3) << 2) | ((t) >> 2))

// ---------------------------------------------------------------------------
// Two-buffer FFT (fwd/prep): 2 barriers.
// ---------------------------------------------------------------------------
template <bool INV>
__device__ __forceinline__ void fft_mid(float2* a, float2* X, float2* Y,
                                        const float2* T1, const float2* Ta, int tid) {
    const int rlo = tid & 15, rhi = tid >> 4;
    dft16<INV>(a);
    #pragma unroll
    for (int t = 0; t < 16; t++) X[swz(tid * 16 + t)] = a[PERM(t)];
    __syncthreads();
    #pragma unroll
    for (int t = 0; t < 16; t++) a[t] = X[swz(tid + t * 256)];
    #pragma unroll
    for (int t = 1; t < 16; t++) {
        float2 w = T1[t * 16 + rlo];
        if (INV) w.y = -w.y;
        a[t] = cmul(a[t], w);
    }
    dft16<INV>(a);
    {
        int o = rhi * 256 + rlo;
        #pragma unroll
        for (int t = 0; t < 16; t++) Y[swz(o + t * 16)] = a[PERM(t)];
    }
    __syncthreads();
    #pragma unroll
    for (int t = 0; t < 16; t++) a[t] = Y[swz(tid + t * 256)];
    #pragma unroll
    for (int t = 1; t < 16; t++) {
        float2 wa = Ta[t * 16 + rlo];
        float2 wb = T1[t * 16 + rhi];
        if (INV) { wa.y = -wa.y; wb.y = -wb.y; }
        a[t] = cmul(a[t], cmul(wa, wb));
    }
    dft16<INV>(a);
}

__device__ __forceinline__ void make_tables(float2* T1, float2* Ta, int tid) {
    int t = tid >> 4, r = tid & 15;
    float s_, c_;
    sincospif(2.0f * (float)(16 * t * r) / (float)NFFT, &s_, &c_);
    T1[tid] = make_float2(c_, -s_);
    sincospif(2.0f * (float)(t * r) / (float)NFFT, &s_, &c_);
    Ta[tid] = make_float2(c_, -s_);
}

__device__ __forceinline__ float extval(const float* __restrict__ xb, int j) {
    if (j < PAD)               return 2.0f * xb[0] - xb[PAD - j];
    if (j < PAD + SEQLEN)      return xb[j - PAD];
    if (j < EXTLEN) {
        int jr = j - (PAD + SEQLEN);
        return 2.0f * xb[SEQLEN - 1] - xb[SEQLEN - 2 - jr];
    }
    return 0.0f;
}

__device__ __forceinline__ void stcs(float* p, float v) {
    asm volatile("st.global.cs.f32 [%0], %1;" :: "l"(p), "f"(v) : "memory");
}

// 16B async copy gmem -> smem
__device__ __forceinline__ void cpasync16(uint32_t dst, const void* src) {
    asm volatile("cp.async.cg.shared.global [%0], [%1], 16;" :: "r"(dst), "l"(src) : "memory");
}
#define CP_COMMIT() asm volatile("cp.async.commit_group;" ::: "memory")
#define CP_WAIT0()  asm volatile("cp.async.wait_group 0;" ::: "memory")

// ---------------------------------------------------------------------------
// fused forward + prep (unchanged from R15)
// ---------------------------------------------------------------------------
__global__ __launch_bounds__(NT, 3) void fwd_kernel(const float* __restrict__ x,
                                                    const float* __restrict__ kern) {
    extern __shared__ float2 sm[];
    float2* X = sm; float2* Y = sm + 4096; float2* T1 = sm + 8192; float2* Ta = sm + 8448;
    int s = blockIdx.x, bp = blockIdx.y, tid = threadIdx.x;
    int cta = bp * NSEG + s;
    make_tables(T1, Ta, tid);
    const float* xa = x + (size_t)(2 * bp) * SEQLEN;
    const float* xb = xa + SEQLEN;
    int j0 = s * SEGSTEP + tid;
    float2 a[16];
    #pragma unroll
    for (int t = 0; t < 16; t++) {
        int j = j0 + t * 256;
        a[t] = make_float2(extval(xa, j), extval(xb, j));
    }
    __syncthreads();                        // tables ready
    fft_mid<false>(a, X, Y, T1, Ta, tid);
    float2* sp = g_spec + (size_t)cta * NFFT;
    #pragma unroll
    for (int t = 0; t < 16; t++)
        sp[tid + t * 256] = a[PERM(t)];

    if (cta < NBANDS) {
        __syncthreads();
        float* sk = (float*)X;
        const float* kb = kern + cta * TAPS;
        for (int i = tid; i < TAPS; i += NT) sk[i] = kb[i];
        __syncthreads();
        #pragma unroll
        for (int t = 0; t < 16; t++) {
            int j = tid + t * 256;
            int m = (j <= PAD) ? j : ((j >= NFFT - PAD) ? NFFT - j : -1);
            float s0 = 0.0f, s1 = 0.0f, s2 = 0.0f, s3 = 0.0f;
            if (m >= 0) {
                int len = TAPS - m;
                int j2 = 0;
                for (; j2 + 3 < len; j2 += 4) {
                    s0 = fmaf(sk[j2],     sk[j2 + m],     s0);
                    s1 = fmaf(sk[j2 + 1], sk[j2 + 1 + m], s1);
                    s2 = fmaf(sk[j2 + 2], sk[j2 + 2 + m], s2);
                    s3 = fmaf(sk[j2 + 3], sk[j2 + 3 + m], s3);
                }
                for (; j2 < len; j2++) s0 = fmaf(sk[j2], sk[j2 + m], s0);
            }
            a[t] = make_float2((s0 + s1) + (s2 + s3), 0.0f);
        }
        __syncthreads();
        fft_mid<false>(a, X, Y, T1, Ta, tid);
        const float invn = 1.0f / (float)NFFT;
        #pragma unroll
        for (int t = 0; t < 16; t++)
            g_H[cta * NFFT + tid + t * 256] = a[PERM(t)].x * invn;
    }
}

// ---------------------------------------------------------------------------
// inverse: 4 CTAs/SM, in-place FFT, cp.async pipeline of next item's Z into X
// ---------------------------------------------------------------------------
__global__ __launch_bounds__(NT, 4) void inv_kernel(float* __restrict__ out) {
    extern __shared__ float2 sm[];
    float2* X = sm; float2* T1 = sm + 4096; float2* Ta = sm + 4352;
    const int tid = threadIdx.x;
    const int rlo = tid & 15, rhi = tid >> 4;
    make_tables(T1, Ta, tid);
    const uint32_t xb4 = (uint32_t)__cvta_generic_to_shared(X) + tid * 16;

    // prologue: prefetch first item's Z into X (linear float4 layout)
    if ((int)blockIdx.x < NITEMS) {
        const float4* sp4 = (const float4*)(g_spec + (size_t)(blockIdx.x % NPAIR) * NFFT);
        #pragma unroll
        for (int u = 0; u < 8; u++)
            cpasync16(xb4 + u * 4096, sp4 + tid + u * 256);
        CP_COMMIT();
    }
    CP_WAIT0();
    __syncthreads();                        // Z + tables visible

    for (int item = blockIdx.x; item < NITEMS; item += PCTAS) {
        int band = item / NPAIR;
        int pair = item - band * NPAIR;     // = bp*NSEG + s
        int bp   = pair / NSEG;
        int s    = pair - bp * NSEG;
        const float* Hb = g_H + (size_t)band * NFFT;

        // a[t] = H * Z   (Z from smem linear; H LDG overlaps the LDS)
        float2 a[16];
        #pragma unroll
        for (int t = 0; t < 16; t++) {
            float  h = Hb[tid + t * 256];
            float2 z = X[tid + t * 256];
            a[t] = make_float2(z.x * h, z.y * h);
        }
        __syncthreads();                    // Z fully read before X overwrite

        // stage 0 (L=1)
        dft16<true>(a);
        #pragma unroll
        for (int t = 0; t < 16; t++) X[swz(tid * 16 + t)] = a[PERM(t)];
        __syncthreads();
        // stage 1 (L=16), in place
        #pragma unroll
        for (int t = 0; t < 16; t++) a[t] = X[swz(tid + t * 256)];
        __syncthreads();
        #pragma unroll
        for (int t = 1; t < 16; t++) {
            float2 w = T1[t * 16 + rlo];
            w.y = -w.y;
            a[t] = cmul(a[t], w);
        }
        dft16<true>(a);
        {
            int o = rhi * 256 + rlo;
            #pragma unroll
            for (int t = 0; t < 16; t++) X[swz(o + t * 16)] = a[PERM(t)];
        }
        __syncthreads();
        // stage 2 (L=256): loads, then X is free -> prefetch next item's Z
        #pragma unroll
        for (int t = 0; t < 16; t++) a[t] = X[swz(tid + t * 256)];
        __syncthreads();                    // all stage-2 reads done

        int nit = item + PCTAS;
        if (nit < NITEMS) {
            const float4* sp4 = (const float4*)(g_spec + (size_t)(nit % NPAIR) * NFFT);
            #pragma unroll
            for (int u = 0; u < 8; u++)
                cpasync16(xb4 + u * 4096, sp4 + tid + u * 256);
            CP_COMMIT();
        }

        // stage-2 twiddles + final dft16 (overlaps the async copy)
        #pragma unroll
        for (int t = 1; t < 16; t++) {
            float2 wa = Ta[t * 16 + rlo];
            float2 wb = T1[t * 16 + rhi];
            wa.y = -wa.y; wb.y = -wb.y;
            a[t] = cmul(a[t], cmul(wa, wb));
        }
        dft16<true>(a);

        // outputs: j = tid + t*256, valid t = 2..13
        size_t basea = ((size_t)(2 * bp) * NBANDS + band) * SEQLEN;
        size_t baseb = basea + (size_t)NBANDS * SEQLEN;
        int pos0 = s * SEGSTEP - PAD + tid;
        #pragma unroll
        for (int t = 2; t <= 13; t++) {
            int pos = pos0 + t * 256;
            if (pos < SEQLEN) {
                float2 y = a[PERM(t)];
                stcs(out + basea + pos, y.x);
                stcs(out + baseb + pos, y.y);
            }
        }

        CP_WAIT0();
        __syncthreads();                    // next item's Z visible to all
    }
}

// ---------------------------------------------------------------------------
extern "C" void kernel_launch(void* const* d_in, const int* in_sizes, int n_in,
                              void* d_out, int out_size) {
    (void)in_sizes; (void)n_in; (void)out_size;
    const float* x    = (const float*)d_in[0];
    const float* kern = (const float*)d_in[1];
    float* out = (float*)d_out;

    cudaFuncSetAttribute(fwd_kernel, cudaFuncAttributeMaxDynamicSharedMemorySize, FWD_SH);
    cudaFuncSetAttribute(inv_kernel, cudaFuncAttributeMaxDynamicSharedMemorySize, INV_SH);

    fwd_kernel<<<dim3(NSEG, BATCH / 2), NT, FWD_SH>>>(x, kern);
    inv_kernel<<<PCTAS, NT, INV_SH>>>(out);
}

// round 17
// speedup vs baseline: 1.0695x; 1.0695x over previous
#include <cuda_runtime.h>
#include <cstdint>

// ---------------- problem constants ----------------
#define BATCH    128
#define SEQLEN   16384
#define NBANDS   20
#define TAPS     513
#define PAD      512
#define EXTLEN   (SEQLEN + 2*PAD)            // 17408

// ---------------- FFT / overlap-save config ----------------
#define NFFT     4096
#define SEGSTEP  3072
#define NSEG     6
#define NPAIR    ((BATCH/2)*NSEG)            // 384 fwd units
#define NT       256
#define NITEMS   (NBANDS*NPAIR)              // 7680 inverse items
#define PCTAS    (148*4)                     // 592 persistent CTAs (4/SM)
#define NUNITS   (NPAIR + NBANDS)            // 404 producer units

// smem: X[4096] T1[256] Ta[256] float2 = 36 KB
#define INV_SH   ((4096 + 512) * 8)          // 36864

// ---------------- device scratch ----------------
__device__ float2 g_spec[NPAIR * NFFT];
__device__ float  g_H[NBANDS * NFFT];
__device__ int    g_ctr;
__device__ int    g_flags[NUNITS];

__device__ __forceinline__ int swz(int i) { return i ^ ((i >> 4) & 15); }

// FFMA-imm add/sub: x+y / x-y as fma(x, ±1.0, y) — rt_SMSP=1, bit-exact.
__device__ __forceinline__ float fadd1(float x, float y) {
    float r; asm("fma.rn.f32 %0, %1, 0f3F800000, %2;" : "=f"(r) : "f"(x), "f"(y)); return r;
}
__device__ __forceinline__ float fsub1(float x, float y) {   // x - y
    float r; asm("fma.rn.f32 %0, %1, 0fBF800000, %2;" : "=f"(r) : "f"(y), "f"(x)); return r;
}

__device__ __forceinline__ float2 cmul(float2 a, float2 b) {
    return make_float2(fmaf(a.x, b.x, -a.y * b.y), fmaf(a.x, b.y, a.y * b.x));
}
template <bool INV>
__device__ __forceinline__ float2 cmulc(float2 a, float cx, float cy) {
    if (INV) cy = -cy;
    float m = a.y * cy;
    float n = a.y * cx;
    return make_float2(fmaf(a.x, cx, -m), fmaf(a.x, cy, n));
}

template <bool INV>
__device__ __forceinline__ void dft4(float2& x0, float2& x1, float2& x2, float2& x3) {
    float t0x = fadd1(x0.x, x2.x), t0y = fadd1(x0.y, x2.y);
    float t1x = fsub1(x0.x, x2.x), t1y = fsub1(x0.y, x2.y);
    float t2x = fadd1(x1.x, x3.x), t2y = fadd1(x1.y, x3.y);
    float t3x = fsub1(x1.x, x3.x), t3y = fsub1(x1.y, x3.y);
    x0 = make_float2(fadd1(t0x, t2x), fadd1(t0y, t2y));
    x2 = make_float2(fsub1(t0x, t2x), fsub1(t0y, t2y));
    if (!INV) {
        x1 = make_float2(fadd1(t1x, t3y), fsub1(t1y, t3x));
        x3 = make_float2(fsub1(t1x, t3y), fadd1(t1y, t3x));
    } else {
        x1 = make_float2(fsub1(t1x, t3y), fadd1(t1y, t3x));
        x3 = make_float2(fadd1(t1x, t3y), fsub1(t1y, t3x));
    }
}

#define W1X  0.92387953251128674f
#define W1Y -0.38268343236508978f
#define W2X  0.70710678118654752f
#define W2Y -0.70710678118654752f
#define W3X  0.38268343236508978f
#define W3Y -0.92387953251128674f
#define W6X -0.70710678118654752f
#define W6Y -0.70710678118654752f
#define W9X -0.92387953251128674f
#define W9Y  0.38268343236508978f

template <bool INV>
__device__ __forceinline__ void dft16(float2* a) {
    #pragma unroll
    for (int n0 = 0; n0 < 4; n0++)
        dft4<INV>(a[n0], a[n0 + 4], a[n0 + 8], a[n0 + 12]);
    a[5]  = cmulc<INV>(a[5],  W1X, W1Y);
    a[9]  = cmulc<INV>(a[9],  W2X, W2Y);
    a[13] = cmulc<INV>(a[13], W3X, W3Y);
    a[6]  = cmulc<INV>(a[6],  W2X, W2Y);
    a[10] = INV ? make_float2(-a[10].y, a[10].x) : make_float2(a[10].y, -a[10].x);
    a[14] = cmulc<INV>(a[14], W6X, W6Y);
    a[7]  = cmulc<INV>(a[7],  W3X, W3Y);
    a[11] = cmulc<INV>(a[11], W6X, W6Y);
    a[15] = cmulc<INV>(a[15], W9X, W9Y);
    #pragma unroll
    for (int k0 = 0; k0 < 4; k0++)
        dft4<INV>(a[4 * k0], a[4 * k0 + 1], a[4 * k0 + 2], a[4 * k0 + 3]);
}
#define PERM(t) ((((t) & 3) << 2) | ((t) >> 2))

// ---------------------------------------------------------------------------
// In-place FFT-4096, single X buffer, 3 internal barriers. Tables are stored
// INVERSE-sense (+sin); forward paths (INV=false) negate per use.
// Caller provides a trailing barrier before X is rewritten.
// ---------------------------------------------------------------------------
template <bool INV>
__device__ __forceinline__ void fft_ip(float2* a, float2* X,
                                       const float2* T1, const float2* Ta,
                                       int tid, int rlo, int rhi) {
    dft16<INV>(a);
    #pragma unroll
    for (int t = 0; t < 16; t++) X[swz(tid * 16 + t)] = a[PERM(t)];
    __syncthreads();
    #pragma unroll
    for (int t = 0; t < 16; t++) a[t] = X[swz(tid + t * 256)];
    __syncthreads();                        // all reads before in-place writes
    #pragma unroll
    for (int t = 1; t < 16; t++) {
        float2 w = T1[t * 16 + rlo];
        if (!INV) w.y = -w.y;               // tables are inverse-sense
        a[t] = cmul(a[t], w);
    }
    dft16<INV>(a);
    {
        int o = rhi * 256 + rlo;
        #pragma unroll
        for (int t = 0; t < 16; t++) X[swz(o + t * 16)] = a[PERM(t)];
    }
    __syncthreads();
    #pragma unroll
    for (int t = 0; t < 16; t++) a[t] = X[swz(tid + t * 256)];
    #pragma unroll
    for (int t = 1; t < 16; t++) {
        float2 wa = Ta[t * 16 + rlo];
        float2 wb = T1[t * 16 + rhi];
        if (!INV) { wa.y = -wa.y; wb.y = -wb.y; }
        a[t] = cmul(a[t], cmul(wa, wb));
    }
    dft16<INV>(a);
}

__device__ __forceinline__ float extval(const float* __restrict__ xb, int j) {
    if (j < PAD)               return 2.0f * xb[0] - xb[PAD - j];
    if (j < PAD + SEQLEN)      return xb[j - PAD];
    if (j < EXTLEN) {
        int jr = j - (PAD + SEQLEN);
        return 2.0f * xb[SEQLEN - 1] - xb[SEQLEN - 2 - jr];
    }
    return 0.0f;
}

__device__ __forceinline__ void stcs(float* p, float v) {
    asm volatile("st.global.cs.f32 [%0], %1;" :: "l"(p), "f"(v) : "memory");
}

// ---------------------------------------------------------------------------
__global__ void init_kernel() {
    int i = blockIdx.x * blockDim.x + threadIdx.x;
    if (i == 0) g_ctr = 0;
    if (i < NUNITS) g_flags[i] = 0;
}

// ---------------------------------------------------------------------------
// Fused persistent kernel.
// Phase 1 (work-stolen): units 0..383 = forward segment FFTs -> g_spec;
//                        units 384..403 = band autocorr+FFT -> g_H.
//   Each unit: stores; __syncthreads; tid0: __threadfence + flag release.
// Phase 2: inverse items; tid0/tid32 poll the (pair, band) flags, barrier,
//   then H*Z -> inverse FFT -> streamed output stores.
// ---------------------------------------------------------------------------
__global__ __launch_bounds__(NT, 4) void fused_kernel(const float* __restrict__ x,
                                                      const float* __restrict__ kern,
                                                      float* __restrict__ out) {
    extern __shared__ float2 sm[];
    float2* X = sm; float2* T1 = sm + 4096; float2* Ta = sm + 4352;
    __shared__ int s_u;
    const int tid = threadIdx.x;
    const int rlo = tid & 15, rhi = tid >> 4;

    // inverse-sense twiddle tables (+sin)
    {
        int t = tid >> 4, r = tid & 15;
        float s_, c_;
        sincospif(2.0f * (float)(16 * t * r) / (float)NFFT, &s_, &c_);
        T1[tid] = make_float2(c_, s_);
        sincospif(2.0f * (float)(t * r) / (float)NFFT, &s_, &c_);
        Ta[tid] = make_float2(c_, s_);
    }
    __syncthreads();

    // ---------------- phase 1: work-steal producer units ----------------
    for (;;) {
        if (tid == 0) s_u = atomicAdd(&g_ctr, 1);
        __syncthreads();
        int u = s_u;
        if (u >= NUNITS) break;             // uniform exit
        float2 a[16];
        if (u < NPAIR) {
            // forward segment: pair u = bp*NSEG + s
            int bp = u / NSEG, s = u - bp * NSEG;
            const float* xa = x + (size_t)(2 * bp) * SEQLEN;
            const float* xb = xa + SEQLEN;
            int j0 = s * SEGSTEP + tid;
            #pragma unroll
            for (int t = 0; t < 16; t++) {
                int j = j0 + t * 256;
                a[t] = make_float2(extval(xa, j), extval(xb, j));
            }
            fft_ip<false>(a, X, T1, Ta, tid, rlo, rhi);
            float2* sp = g_spec + (size_t)u * NFFT;
            #pragma unroll
            for (int t = 0; t < 16; t++)
                sp[tid + t * 256] = a[PERM(t)];
        } else {
            // band prep: autocorr + forward FFT -> g_H
            int band = u - NPAIR;
            float* sk = (float*)X;          // 513 floats
            const float* kb = kern + band * TAPS;
            for (int i = tid; i < TAPS; i += NT) sk[i] = kb[i];
            __syncthreads();
            #pragma unroll
            for (int t = 0; t < 16; t++) {
                int j = tid + t * 256;
                int m = (j <= PAD) ? j : ((j >= NFFT - PAD) ? NFFT - j : -1);
                float s0 = 0.0f, s1 = 0.0f, s2 = 0.0f, s3 = 0.0f;
                if (m >= 0) {
                    int len = TAPS - m;
                    int j2 = 0;
                    for (; j2 + 3 < len; j2 += 4) {
                        s0 = fmaf(sk[j2],     sk[j2 + m],     s0);
                        s1 = fmaf(sk[j2 + 1], sk[j2 + 1 + m], s1);
                        s2 = fmaf(sk[j2 + 2], sk[j2 + 2 + m], s2);
                        s3 = fmaf(sk[j2 + 3], sk[j2 + 3 + m], s3);
                    }
                    for (; j2 < len; j2++) s0 = fmaf(sk[j2], sk[j2 + m], s0);
                }
                a[t] = make_float2((s0 + s1) + (s2 + s3), 0.0f);
            }
            __syncthreads();                // sk reads done before X reuse
            fft_ip<false>(a, X, T1, Ta, tid, rlo, rhi);
            const float invn = 1.0f / (float)NFFT;
            #pragma unroll
            for (int t = 0; t < 16; t++)
                g_H[(size_t)band * NFFT + tid + t * 256] = a[PERM(t)].x * invn;
        }
        // release: all stores done -> fence -> flag
        __syncthreads();
        if (tid == 0) {
            __threadfence();
            *(volatile int*)(g_flags + u) = 1;
        }
        // X free for next unit: the unit-start barrier orders reuse
    }

    // ---------------- phase 2: inverse items ----------------
    for (int item = blockIdx.x; item < NITEMS; item += PCTAS) {
        int band = item / NPAIR;
        int pair = item - band * NPAIR;
        int bp   = pair / NSEG;
        int s    = pair - bp * NSEG;
        // acquire producers
        if (tid == 0)       { volatile int* f = g_flags + pair;          while (*f == 0) {} }
        else if (tid == 32) { volatile int* f = g_flags + NPAIR + band;  while (*f == 0) {} }
        __syncthreads();

        const float*  Hb = g_H + (size_t)band * NFFT;
        const float2* sp = g_spec + (size_t)pair * NFFT;
        float2 a[16];
        #pragma unroll
        for (int t = 0; t < 16; t++) {
            float  h = Hb[tid + t * 256];
            float2 z = sp[tid + t * 256];
            a[t] = make_float2(z.x * h, z.y * h);
        }
        fft_ip<true>(a, X, T1, Ta, tid, rlo, rhi);

        size_t basea = ((size_t)(2 * bp) * NBANDS + band) * SEQLEN;
        size_t baseb = basea + (size_t)NBANDS * SEQLEN;
        int pos0 = s * SEGSTEP - PAD + tid;
        #pragma unroll
        for (int t = 2; t <= 13; t++) {
            int pos = pos0 + t * 256;
            if (pos < SEQLEN) {
                float2 y = a[PERM(t)];
                stcs(out + basea + pos, y.x);
                stcs(out + baseb + pos, y.y);
            }
        }
        __syncthreads();                    // X reads done before next item
    }
}

// ---------------------------------------------------------------------------
extern "C" void kernel_launch(void* const* d_in, const int* in_sizes, int n_in,
                              void* d_out, int out_size) {
    (void)in_sizes; (void)n_in; (void)out_size;
    const float* x    = (const float*)d_in[0];
    const float* kern = (const float*)d_in[1];
    float* out = (float*)d_out;

    cudaFuncSetAttribute(fused_kernel, cudaFuncAttributeMaxDynamicSharedMemorySize, INV_SH);

    init_kernel<<<2, 256>>>();
    fused_kernel<<<PCTAS, NT, INV_SH>>>(x, kern, out);
}